// round 15
// baseline (speedup 1.0000x reference)
#include <cuda_runtime.h>
#include <cuda_fp16.h>
#include <math.h>

#define NN 50000
#define EE 1600000

// ---------------- device scratch (static: no allocs allowed) ----------------
__device__ __half g_fb[NN * 128];    // fp16 projected features (gather operand)
__device__ float g_h1[NN * 128];
__device__ float g_h2[NN * 128];
__device__ float g_res2[NN * 64];
__device__ float g_el[NN * 8];
__device__ float g_er[NN * 8];
__device__ int   g_cnt[NN];
__device__ int   g_rowptr[NN + 1];
__device__ int   g_srcs[EE];

// ---------------- packed f32x2 helpers ----------------
__device__ __forceinline__ unsigned long long pack2(float lo, float hi) {
    unsigned long long r;
    asm("mov.b64 %0, {%1, %2};" : "=l"(r) : "f"(lo), "f"(hi));
    return r;
}
__device__ __forceinline__ void unpack2(unsigned long long v, float& lo, float& hi) {
    asm("mov.b64 {%0, %1}, %2;" : "=f"(lo), "=f"(hi) : "l"(v));
}
__device__ __forceinline__ unsigned long long fma2(unsigned long long a,
                                                   unsigned long long b,
                                                   unsigned long long c) {
    unsigned long long r;
    asm("fma.rn.f32x2 %0, %1, %2, %3;" : "=l"(r) : "l"(a), "l"(b), "l"(c));
    return r;
}
__device__ __forceinline__ unsigned long long add2(unsigned long long a,
                                                   unsigned long long b) {
    unsigned long long r;
    asm("add.rn.f32x2 %0, %1, %2;" : "=l"(r) : "l"(a), "l"(b));
    return r;
}

// ---------------- small utility kernels ----------------
__global__ void zero_int_kernel(int* p, int n) {
    int i = blockIdx.x * blockDim.x + threadIdx.x;
    if (i < n) p[i] = 0;
}

__global__ void hist_kernel(const int* __restrict__ dst, int* __restrict__ cnt, int e) {
    int i = blockIdx.x * blockDim.x + threadIdx.x;
    if (i < e) atomicAdd(&cnt[dst[i]], 1);
}

// single-block full exclusive scan (1024 threads): cnt -> rowptr; zeroes cnt
// (cnt is reused as the fill counter array by scatter_kernel).
__global__ void scan_full_kernel(int* __restrict__ cnt, int* __restrict__ rowptr, int n) {
    __shared__ int wsum[32];
    __shared__ int carry_s;
    int tid = threadIdx.x, lane = tid & 31, wid = tid >> 5;
    if (tid == 0) { carry_s = 0; rowptr[0] = 0; }
    __syncthreads();
    for (int base = 0; base < n; base += 1024) {
        int i = base + tid;
        int v = (i < n) ? cnt[i] : 0;
        int incl = v;
        #pragma unroll
        for (int off = 1; off < 32; off <<= 1) {
            int t = __shfl_up_sync(0xffffffffu, incl, off);
            if (lane >= off) incl += t;
        }
        if (lane == 31) wsum[wid] = incl;
        __syncthreads();
        if (wid == 0) {
            int w = wsum[lane];
            #pragma unroll
            for (int off = 1; off < 32; off <<= 1) {
                int t = __shfl_up_sync(0xffffffffu, w, off);
                if (lane >= off) w += t;
            }
            wsum[lane] = w;
        }
        __syncthreads();
        int woff = (wid > 0 ? wsum[wid - 1] : 0) + carry_s;
        if (i < n) { rowptr[i + 1] = woff + incl; cnt[i] = 0; }
        __syncthreads();
        if (tid == 0) carry_s += wsum[31];
        __syncthreads();
    }
}

__global__ void scatter_kernel(const int* __restrict__ src, const int* __restrict__ dst,
                               const int* __restrict__ rowptr, int* __restrict__ fill,
                               int* __restrict__ srcs, int e) {
    int i = blockIdx.x * blockDim.x + threadIdx.x;
    if (i < e) {
        int d = dst[i];
        int pos = rowptr[d] + atomicAdd(&fill[d], 1);
        srcs[pos] = src[i];
    }
}

// ------- register-tiled GEMM with packed FFMA2 + fused el/er epilogue -------
template <bool DUAL>
__global__ __launch_bounds__(256) void gemm2_kernel(
    const float* __restrict__ X,
    const float* __restrict__ Wa, const float* __restrict__ Wb,
    const float* __restrict__ AL, const float* __restrict__ AR,
    float* __restrict__ outB,
    float* __restrict__ EL, float* __restrict__ ER,
    __half* __restrict__ FB, int n)
{
    __shared__ float xs[128][64];    // [k][swizzled node]
    int tid = threadIdx.x;
    int n0 = blockIdx.x * 64;

    #pragma unroll
    for (int it = 0; it < 8; it++) {
        int idx  = it * 256 + tid;
        int node = idx >> 5;
        int kg   = idx & 31;
        float4 v = make_float4(0.f, 0.f, 0.f, 0.f);
        if (n0 + node < n)
            v = reinterpret_cast<const float4*>(X)[(size_t)(n0 + node) * 32 + kg];
        int pos = 2 * ((node >> 1) ^ (kg & 15)) + (node & 1);
        xs[4 * kg + 0][pos] = v.x;
        xs[4 * kg + 1][pos] = v.y;
        xs[4 * kg + 2][pos] = v.z;
        xs[4 * kg + 3][pos] = v.w;
    }
    __syncthreads();

    int lane = tid & 31, w = tid >> 5;
    int pp0 = w * 4;
    const float* Wp;
    int cl, half = 0;
    if (DUAL) { half = lane >> 4; cl = (lane & 15) * 4; Wp = half ? Wb : Wa; }
    else      { cl = lane * 4; Wp = Wa; }
    const int wstride = DUAL ? 64 : 128;

    unsigned long long acc[4][4];
    #pragma unroll
    for (int j = 0; j < 4; j++)
        #pragma unroll
        for (int p = 0; p < 4; p++) acc[j][p] = 0ull;

    #pragma unroll 2
    for (int k = 0; k < 128; k++) {
        float4 wv = *reinterpret_cast<const float4*>(Wp + k * wstride + cl);
        unsigned long long wd0 = pack2(wv.x, wv.x);
        unsigned long long wd1 = pack2(wv.y, wv.y);
        unsigned long long wd2 = pack2(wv.z, wv.z);
        unsigned long long wd3 = pack2(wv.w, wv.w);
        int f = (k >> 2) & 15;
        unsigned long long xp[4];
        #pragma unroll
        for (int p = 0; p < 4; p++)
            xp[p] = *reinterpret_cast<const unsigned long long*>(
                        &xs[k][2 * ((pp0 + p) ^ f)]);
        #pragma unroll
        for (int p = 0; p < 4; p++) {
            acc[0][p] = fma2(wd0, xp[p], acc[0][p]);
            acc[1][p] = fma2(wd1, xp[p], acc[1][p]);
            acc[2][p] = fma2(wd2, xp[p], acc[2][p]);
            acc[3][p] = fma2(wd3, xp[p], acc[3][p]);
        }
    }

    // ---- fused el/er: per-head dot products from f32 accumulators ----
    unsigned long long elp[4], erp[4];
    #pragma unroll
    for (int p = 0; p < 4; p++) { elp[p] = 0ull; erp[p] = 0ull; }
    #pragma unroll
    for (int j = 0; j < 4; j++) {
        float a = AL[cl + j], r = AR[cl + j];
        unsigned long long ad = pack2(a, a), rd = pack2(r, r);
        #pragma unroll
        for (int p = 0; p < 4; p++) {
            elp[p] = fma2(ad, acc[j][p], elp[p]);
            erp[p] = fma2(rd, acc[j][p], erp[p]);
        }
    }
    constexpr int REDMAX = DUAL ? 8 : 2;
    #pragma unroll
    for (int off = 1; off <= REDMAX; off <<= 1) {
        #pragma unroll
        for (int p = 0; p < 4; p++) {
            elp[p] = add2(elp[p], __shfl_xor_sync(0xffffffffu, elp[p], off));
            erp[p] = add2(erp[p], __shfl_xor_sync(0xffffffffu, erp[p], off));
        }
    }
    if ((!DUAL && (lane & 3) == 0) || (DUAL && lane == 0)) {
        int head = DUAL ? 0 : (cl >> 4);
        constexpr int HH = DUAL ? 1 : 8;
        #pragma unroll
        for (int p = 0; p < 4; p++) {
            int ng = n0 + (pp0 + p) * 2;
            float e0, e1, r0, r1;
            unpack2(elp[p], e0, e1);
            unpack2(erp[p], r0, r1);
            if (ng < n)     { EL[ng * HH + head] = e0; ER[ng * HH + head] = r0; }
            if (ng + 1 < n) { EL[(ng + 1) * HH + head] = e1; ER[(ng + 1) * HH + head] = r1; }
        }
    }

    // ---- stores: fp16 FB (primary) / f32 outB (DUAL residual half) ----
    const int ostride = DUAL ? 64 : 128;
    bool writeFH = (!DUAL) || (half == 0);
    #pragma unroll
    for (int p = 0; p < 4; p++) {
        int ng = n0 + (pp0 + p) * 2;
        float a0, a1, a2, a3, b0, b1, b2, b3;
        unpack2(acc[0][p], a0, b0);
        unpack2(acc[1][p], a1, b1);
        unpack2(acc[2][p], a2, b2);
        unpack2(acc[3][p], a3, b3);
        if (ng < n) {
            if (writeFH) {
                __half2 q0 = __floats2half2_rn(a0, a1);
                __half2 q1 = __floats2half2_rn(a2, a3);
                uint2 pk = make_uint2(*reinterpret_cast<unsigned int*>(&q0),
                                      *reinterpret_cast<unsigned int*>(&q1));
                *reinterpret_cast<uint2*>(FB + (size_t)ng * ostride + cl) = pk;
            } else {
                *reinterpret_cast<float4*>(outB + (size_t)ng * ostride + cl) =
                    make_float4(a0, a1, a2, a3);
            }
        }
        if (ng + 1 < n) {
            if (writeFH) {
                __half2 q0 = __floats2half2_rn(b0, b1);
                __half2 q1 = __floats2half2_rn(b2, b3);
                uint2 pk = make_uint2(*reinterpret_cast<unsigned int*>(&q0),
                                      *reinterpret_cast<unsigned int*>(&q1));
                *reinterpret_cast<uint2*>(FB + (size_t)(ng + 1) * ostride + cl) = pk;
            } else {
                *reinterpret_cast<float4*>(outB + (size_t)(ng + 1) * ostride + cl) =
                    make_float4(b0, b1, b2, b3);
            }
        }
    }
}

// ---- fused aggregation: single edge pass, fp16 gathers, srcs prefetch ------
template <int H, int D, bool ELU_ACT, bool HAS_RES>
__global__ void fused_layer_kernel(const __half* __restrict__ FB,
                                   const float* __restrict__ EL,
                                   const float* __restrict__ ER,
                                   const int* __restrict__ rowptr,
                                   const int* __restrict__ srcs,
                                   const float* __restrict__ RESP,
                                   const float* __restrict__ B,
                                   float* __restrict__ OUT, int n) {
    constexpr int HD  = H * D;
    constexpr int VPL = HD / 32;     // 4 (HD=128) or 2 (HD=64)
    int gw = (blockIdx.x * blockDim.x + threadIdx.x) >> 5;
    if (gw >= n) return;
    int lane = threadIdx.x & 31;

    constexpr int DSHIFT = (D == 16) ? 4 : 6;
    int col  = lane * VPL;
    int head = col >> DSHIFT;
    float erh = ER[gw * H + head];
    int beg = rowptr[gw], end = rowptr[gw + 1];

    float den = 0.f;
    float acc[VPL];
    #pragma unroll
    for (int j = 0; j < VPL; j++) acc[j] = 0.f;

    int i = beg;
    if (i + 8 <= end) {
        int s[8];
        #pragma unroll
        for (int u = 0; u < 8; u++) s[u] = srcs[i + u];
        while (true) {
            int ni = i + 8;
            bool haveN = (ni + 8 <= end);
            int sn[8];
            if (haveN) {
                #pragma unroll
                for (int u = 0; u < 8; u++) sn[u] = srcs[ni + u];
            }
            float elv[8];
            #pragma unroll
            for (int u = 0; u < 8; u++) elv[u] = EL[s[u] * H + head];
            if constexpr (VPL == 4) {
                uint2 v[8];
                #pragma unroll
                for (int u = 0; u < 8; u++)
                    v[u] = *reinterpret_cast<const uint2*>(FB + (size_t)s[u] * HD + col);
                #pragma unroll
                for (int u = 0; u < 8; u++) {
                    float x = elv[u] + erh;
                    x = x > 0.f ? x : 0.2f * x;
                    float a = __expf(x);
                    den += a;
                    float2 f01 = __half22float2(*reinterpret_cast<__half2*>(&v[u].x));
                    float2 f23 = __half22float2(*reinterpret_cast<__half2*>(&v[u].y));
                    acc[0] += f01.x * a; acc[1] += f01.y * a;
                    acc[2] += f23.x * a; acc[3] += f23.y * a;
                }
            } else {
                unsigned int v[8];
                #pragma unroll
                for (int u = 0; u < 8; u++)
                    v[u] = *reinterpret_cast<const unsigned int*>(FB + (size_t)s[u] * HD + col);
                #pragma unroll
                for (int u = 0; u < 8; u++) {
                    float x = elv[u] + erh;
                    x = x > 0.f ? x : 0.2f * x;
                    float a = __expf(x);
                    den += a;
                    float2 f01 = __half22float2(*reinterpret_cast<__half2*>(&v[u]));
                    acc[0] += f01.x * a; acc[1] += f01.y * a;
                }
            }
            i = ni;
            if (!haveN) break;
            #pragma unroll
            for (int u = 0; u < 8; u++) s[u] = sn[u];
        }
    }
    for (; i < end; i++) {
        int s0 = srcs[i];
        float x = EL[s0 * H + head] + erh;
        x = x > 0.f ? x : 0.2f * x;
        float a = __expf(x);
        den += a;
        if constexpr (VPL == 4) {
            uint2 v = *reinterpret_cast<const uint2*>(FB + (size_t)s0 * HD + col);
            float2 f01 = __half22float2(*reinterpret_cast<__half2*>(&v.x));
            float2 f23 = __half22float2(*reinterpret_cast<__half2*>(&v.y));
            acc[0] += f01.x * a; acc[1] += f01.y * a;
            acc[2] += f23.x * a; acc[3] += f23.y * a;
        } else {
            unsigned int v = *reinterpret_cast<const unsigned int*>(FB + (size_t)s0 * HD + col);
            float2 f01 = __half22float2(*reinterpret_cast<__half2*>(&v));
            acc[0] += f01.x * a; acc[1] += f01.y * a;
        }
    }

    float sinv = (end > beg) ? 1.0f / den : 0.0f;

    float o[VPL];
    #pragma unroll
    for (int j = 0; j < VPL; j++) {
        float v = acc[j] * sinv + B[col + j];
        if constexpr (HAS_RES) v += RESP[gw * HD + col + j];
        if constexpr (ELU_ACT) v = v > 0.f ? v : expm1f(v);
        o[j] = v;
    }
    if constexpr (VPL == 4)
        *reinterpret_cast<float4*>(OUT + gw * HD + col) = make_float4(o[0], o[1], o[2], o[3]);
    else
        *reinterpret_cast<float2*>(OUT + gw * HD + col) = make_float2(o[0], o[1]);
}

// ---------------- launch ----------------
extern "C" void kernel_launch(void* const* d_in, const int* in_sizes, int n_in,
                              void* d_out, int out_size) {
    const float* x     = (const float*)d_in[0];
    const int*   src   = (const int*)d_in[1];
    const int*   dst   = (const int*)d_in[2];
    const float* W0    = (const float*)d_in[3];
    const float* al0   = (const float*)d_in[4];
    const float* ar0   = (const float*)d_in[5];
    const float* b0    = (const float*)d_in[6];
    const float* W1    = (const float*)d_in[7];
    const float* al1   = (const float*)d_in[8];
    const float* ar1   = (const float*)d_in[9];
    const float* b1    = (const float*)d_in[10];
    const float* W2    = (const float*)d_in[11];
    const float* al2   = (const float*)d_in[12];
    const float* ar2   = (const float*)d_in[13];
    const float* b2    = (const float*)d_in[14];
    const float* resW2 = (const float*)d_in[15];
    float* out = (float*)d_out;

    const int n = NN;
    const int e = in_sizes[1];

    void* p;
    cudaGetSymbolAddress(&p, g_fb);     __half* fb_  = (__half*)p;
    cudaGetSymbolAddress(&p, g_h1);     float* h1_   = (float*)p;
    cudaGetSymbolAddress(&p, g_h2);     float* h2_   = (float*)p;
    cudaGetSymbolAddress(&p, g_res2);   float* res2_ = (float*)p;
    cudaGetSymbolAddress(&p, g_el);     float* el_   = (float*)p;
    cudaGetSymbolAddress(&p, g_er);     float* er_   = (float*)p;
    cudaGetSymbolAddress(&p, g_cnt);    int*   cnt_  = (int*)p;
    cudaGetSymbolAddress(&p, g_rowptr); int*   rp_   = (int*)p;
    cudaGetSymbolAddress(&p, g_srcs);   int*   srcs_ = (int*)p;

    const int TB = 256;
    int nb_n   = (n + TB - 1) / TB;
    int nb_e   = (e + TB - 1) / TB;
    int nb_w   = (n + 7) / 8;
    int nb_g   = (n + 63) / 64;

    // ---- (0) layer-0 GEMM first (independent of CSR build) ----
    gemm2_kernel<false><<<nb_g, 256>>>(x, W0, nullptr, al0, ar0,
                                       nullptr, el_, er_, fb_, n);

    // ---- CSR build (sorted by dst): zero(1), hist(2), scan(3), scatter(4) --
    zero_int_kernel<<<nb_n, TB>>>(cnt_, n);
    hist_kernel<<<nb_e, TB>>>(dst, cnt_, e);
    scan_full_kernel<<<1, 1024>>>(cnt_, rp_, n);   // also zeroes cnt for scatter
    scatter_kernel<<<nb_e, TB>>>(src, dst, rp_, cnt_, srcs_, e);

    // ---- layer 0 fused (5) ----
    fused_layer_kernel<8, 16, true, false><<<nb_w, TB>>>(fb_, el_, er_, rp_, srcs_,
                                                         nullptr, b0, h1_, n);

    // ---- layer 1: 128 -> 8x16, identity residual, ELU ----
    gemm2_kernel<false><<<nb_g, 256>>>(h1_, W1, nullptr, al1, ar1,
                                       nullptr, el_, er_, fb_, n);
    fused_layer_kernel<8, 16, true, true><<<nb_w, TB>>>(fb_, el_, er_, rp_, srcs_,
                                                        h1_, b1, h2_, n);

    // ---- layer 2: 128 -> 1x64 (+ linear residual GEMM fused), no act ----
    gemm2_kernel<true><<<nb_g, 256>>>(h2_, W2, resW2, al2, ar2,
                                      res2_, el_, er_, fb_, n);
    fused_layer_kernel<1, 64, false, true><<<nb_w, TB>>>(fb_, el_, er_, rp_, srcs_,
                                                         res2_, b2, out, n);
}

// round 16
// speedup vs baseline: 1.0978x; 1.0978x over previous
#include <cuda_runtime.h>
#include <cuda_fp16.h>
#include <math.h>

#define NN 50000
#define EE 1600000

// ---------------- device scratch (static: no allocs allowed) ----------------
__device__ __half g_fb[NN * 128];    // fp16 projected features (gather operand)
__device__ float g_h1[NN * 128];
__device__ float g_h2[NN * 128];
__device__ float g_res2[NN * 64];
__device__ float g_el[NN * 8];
__device__ float g_er[NN * 8];
__device__ int   g_cnt[NN];          // zero at entry (static init / restored by last kernel)
__device__ int   g_rowptr[NN + 1];
__device__ int   g_cursor[NN + 1];
__device__ int   g_bsum[64];
__device__ int   g_srcs[EE];

// ---------------- packed f32x2 helpers ----------------
__device__ __forceinline__ unsigned long long pack2(float lo, float hi) {
    unsigned long long r;
    asm("mov.b64 %0, {%1, %2};" : "=l"(r) : "f"(lo), "f"(hi));
    return r;
}
__device__ __forceinline__ void unpack2(unsigned long long v, float& lo, float& hi) {
    asm("mov.b64 {%0, %1}, %2;" : "=f"(lo), "=f"(hi) : "l"(v));
}
__device__ __forceinline__ unsigned long long fma2(unsigned long long a,
                                                   unsigned long long b,
                                                   unsigned long long c) {
    unsigned long long r;
    asm("fma.rn.f32x2 %0, %1, %2, %3;" : "=l"(r) : "l"(a), "l"(b), "l"(c));
    return r;
}
__device__ __forceinline__ unsigned long long add2(unsigned long long a,
                                                   unsigned long long b) {
    unsigned long long r;
    asm("add.rn.f32x2 %0, %1, %2;" : "=l"(r) : "l"(a), "l"(b));
    return r;
}

// ---------------- CSR build kernels ----------------
__global__ void hist_kernel(const int* __restrict__ dst, int* __restrict__ cnt, int e) {
    int i = blockIdx.x * blockDim.x + threadIdx.x;
    if (i < e) atomicAdd(&cnt[dst[i]], 1);
}

// block-local scan (1024 elems/block, 256 threads, 4 elems/thread)
__global__ void scan_local_kernel(const int* __restrict__ cnt, int* __restrict__ rowptr,
                                  int* __restrict__ bsum, int n) {
    __shared__ int wsum[8];
    int tid = threadIdx.x, lane = tid & 31, wid = tid >> 5;
    int base = blockIdx.x * 1024 + tid * 4;
    int v0 = (base     < n) ? cnt[base]     : 0;
    int v1 = (base + 1 < n) ? cnt[base + 1] : 0;
    int v2 = (base + 2 < n) ? cnt[base + 2] : 0;
    int v3 = (base + 3 < n) ? cnt[base + 3] : 0;
    int s0 = v0, s1 = s0 + v1, s2 = s1 + v2, s3 = s2 + v3;
    int incl = s3;
    #pragma unroll
    for (int off = 1; off < 32; off <<= 1) {
        int t = __shfl_up_sync(0xffffffffu, incl, off);
        if (lane >= off) incl += t;
    }
    if (lane == 31) wsum[wid] = incl;
    __syncthreads();
    if (wid == 0) {
        int w = (lane < 8) ? wsum[lane] : 0;
        #pragma unroll
        for (int off = 1; off < 8; off <<= 1) {
            int t = __shfl_up_sync(0xffffffffu, w, off);
            if (lane >= off) w += t;
        }
        if (lane < 8) wsum[lane] = w;
    }
    __syncthreads();
    int woff = (wid > 0) ? wsum[wid - 1] : 0;
    int excl = incl - s3 + woff;
    if (base     < n) rowptr[base + 1] = excl + s0;
    if (base + 1 < n) rowptr[base + 2] = excl + s1;
    if (base + 2 < n) rowptr[base + 3] = excl + s2;
    if (base + 3 < n) rowptr[base + 4] = excl + s3;
    __syncthreads();
    if (tid == 255) bsum[blockIdx.x] = wsum[7];
}

// each block redundantly scans bsum (<=64 entries) in smem, then finalizes
// rowptr and writes the cursor copy used by scatter's atomics.
__global__ void scan_add2_kernel(const int* __restrict__ bsum, int nb,
                                 int* __restrict__ rowptr, int* __restrict__ cursor,
                                 int n) {
    __shared__ int bin[64];
    int tid = threadIdx.x;
    if (tid < 32) {
        int v0 = (tid < nb) ? bsum[tid] : 0;
        int v1 = (tid + 32 < nb) ? bsum[tid + 32] : 0;
        int s = v0;
        #pragma unroll
        for (int off = 1; off < 32; off <<= 1) {
            int t = __shfl_up_sync(0xffffffffu, s, off);
            if ((tid & 31) >= off) s += t;
        }
        bin[tid] = s;
        int tot = __shfl_sync(0xffffffffu, s, 31);
        int s1 = v1;
        #pragma unroll
        for (int off = 1; off < 32; off <<= 1) {
            int t = __shfl_up_sync(0xffffffffu, s1, off);
            if ((tid & 31) >= off) s1 += t;
        }
        bin[tid + 32] = s1 + tot;
    }
    __syncthreads();
    int i = blockIdx.x * blockDim.x + tid;
    if (i < n) {
        int b = i >> 10;
        int off = (b == 0) ? 0 : bin[b - 1];
        int val = rowptr[i + 1] + off;
        rowptr[i + 1] = val;
        cursor[i + 1] = val;
    }
    if (i == 0) { rowptr[0] = 0; cursor[0] = 0; }
}

__global__ void scatter_kernel(const int* __restrict__ src, const int* __restrict__ dst,
                               int* __restrict__ cursor, int* __restrict__ srcs, int e) {
    int i = blockIdx.x * blockDim.x + threadIdx.x;
    if (i < e) {
        int pos = atomicAdd(&cursor[dst[i]], 1);
        srcs[pos] = src[i];
    }
}

// ------- register-tiled GEMM with packed FFMA2 + fused el/er epilogue -------
template <bool DUAL>
__global__ __launch_bounds__(256) void gemm2_kernel(
    const float* __restrict__ X,
    const float* __restrict__ Wa, const float* __restrict__ Wb,
    const float* __restrict__ AL, const float* __restrict__ AR,
    float* __restrict__ outB,
    float* __restrict__ EL, float* __restrict__ ER,
    __half* __restrict__ FB, int n)
{
    __shared__ float xs[128][64];    // [k][swizzled node]
    int tid = threadIdx.x;
    int n0 = blockIdx.x * 64;

    #pragma unroll
    for (int it = 0; it < 8; it++) {
        int idx  = it * 256 + tid;
        int node = idx >> 5;
        int kg   = idx & 31;
        float4 v = make_float4(0.f, 0.f, 0.f, 0.f);
        if (n0 + node < n)
            v = reinterpret_cast<const float4*>(X)[(size_t)(n0 + node) * 32 + kg];
        int pos = 2 * ((node >> 1) ^ (kg & 15)) + (node & 1);
        xs[4 * kg + 0][pos] = v.x;
        xs[4 * kg + 1][pos] = v.y;
        xs[4 * kg + 2][pos] = v.z;
        xs[4 * kg + 3][pos] = v.w;
    }
    __syncthreads();

    int lane = tid & 31, w = tid >> 5;
    int pp0 = w * 4;
    const float* Wp;
    int cl, half = 0;
    if (DUAL) { half = lane >> 4; cl = (lane & 15) * 4; Wp = half ? Wb : Wa; }
    else      { cl = lane * 4; Wp = Wa; }
    const int wstride = DUAL ? 64 : 128;

    unsigned long long acc[4][4];
    #pragma unroll
    for (int j = 0; j < 4; j++)
        #pragma unroll
        for (int p = 0; p < 4; p++) acc[j][p] = 0ull;

    #pragma unroll 2
    for (int k = 0; k < 128; k++) {
        float4 wv = *reinterpret_cast<const float4*>(Wp + k * wstride + cl);
        unsigned long long wd0 = pack2(wv.x, wv.x);
        unsigned long long wd1 = pack2(wv.y, wv.y);
        unsigned long long wd2 = pack2(wv.z, wv.z);
        unsigned long long wd3 = pack2(wv.w, wv.w);
        int f = (k >> 2) & 15;
        unsigned long long xp[4];
        #pragma unroll
        for (int p = 0; p < 4; p++)
            xp[p] = *reinterpret_cast<const unsigned long long*>(
                        &xs[k][2 * ((pp0 + p) ^ f)]);
        #pragma unroll
        for (int p = 0; p < 4; p++) {
            acc[0][p] = fma2(wd0, xp[p], acc[0][p]);
            acc[1][p] = fma2(wd1, xp[p], acc[1][p]);
            acc[2][p] = fma2(wd2, xp[p], acc[2][p]);
            acc[3][p] = fma2(wd3, xp[p], acc[3][p]);
        }
    }

    // ---- fused el/er: per-head dot products from f32 accumulators ----
    unsigned long long elp[4], erp[4];
    #pragma unroll
    for (int p = 0; p < 4; p++) { elp[p] = 0ull; erp[p] = 0ull; }
    #pragma unroll
    for (int j = 0; j < 4; j++) {
        float a = AL[cl + j], r = AR[cl + j];
        unsigned long long ad = pack2(a, a), rd = pack2(r, r);
        #pragma unroll
        for (int p = 0; p < 4; p++) {
            elp[p] = fma2(ad, acc[j][p], elp[p]);
            erp[p] = fma2(rd, acc[j][p], erp[p]);
        }
    }
    constexpr int REDMAX = DUAL ? 8 : 2;
    #pragma unroll
    for (int off = 1; off <= REDMAX; off <<= 1) {
        #pragma unroll
        for (int p = 0; p < 4; p++) {
            elp[p] = add2(elp[p], __shfl_xor_sync(0xffffffffu, elp[p], off));
            erp[p] = add2(erp[p], __shfl_xor_sync(0xffffffffu, erp[p], off));
        }
    }
    if ((!DUAL && (lane & 3) == 0) || (DUAL && lane == 0)) {
        int head = DUAL ? 0 : (cl >> 4);
        constexpr int HH = DUAL ? 1 : 8;
        #pragma unroll
        for (int p = 0; p < 4; p++) {
            int ng = n0 + (pp0 + p) * 2;
            float e0, e1, r0, r1;
            unpack2(elp[p], e0, e1);
            unpack2(erp[p], r0, r1);
            if (ng < n)     { EL[ng * HH + head] = e0; ER[ng * HH + head] = r0; }
            if (ng + 1 < n) { EL[(ng + 1) * HH + head] = e1; ER[(ng + 1) * HH + head] = r1; }
        }
    }

    // ---- stores: fp16 FB (primary) / f32 outB (DUAL residual half) ----
    const int ostride = DUAL ? 64 : 128;
    bool writeFH = (!DUAL) || (half == 0);
    #pragma unroll
    for (int p = 0; p < 4; p++) {
        int ng = n0 + (pp0 + p) * 2;
        float a0, a1, a2, a3, b0, b1, b2, b3;
        unpack2(acc[0][p], a0, b0);
        unpack2(acc[1][p], a1, b1);
        unpack2(acc[2][p], a2, b2);
        unpack2(acc[3][p], a3, b3);
        if (ng < n) {
            if (writeFH) {
                __half2 q0 = __floats2half2_rn(a0, a1);
                __half2 q1 = __floats2half2_rn(a2, a3);
                uint2 pk = make_uint2(*reinterpret_cast<unsigned int*>(&q0),
                                      *reinterpret_cast<unsigned int*>(&q1));
                *reinterpret_cast<uint2*>(FB + (size_t)ng * ostride + cl) = pk;
            } else {
                *reinterpret_cast<float4*>(outB + (size_t)ng * ostride + cl) =
                    make_float4(a0, a1, a2, a3);
            }
        }
        if (ng + 1 < n) {
            if (writeFH) {
                __half2 q0 = __floats2half2_rn(b0, b1);
                __half2 q1 = __floats2half2_rn(b2, b3);
                uint2 pk = make_uint2(*reinterpret_cast<unsigned int*>(&q0),
                                      *reinterpret_cast<unsigned int*>(&q1));
                *reinterpret_cast<uint2*>(FB + (size_t)(ng + 1) * ostride + cl) = pk;
            } else {
                *reinterpret_cast<float4*>(outB + (size_t)(ng + 1) * ostride + cl) =
                    make_float4(b0, b1, b2, b3);
            }
        }
    }
}

// ---- fused aggregation: single edge pass, fp16 gathers, srcs prefetch ------
// CNT != nullptr on the LAST layer: restores cnt==0 invariant for next call.
template <int H, int D, bool ELU_ACT, bool HAS_RES>
__global__ void fused_layer_kernel(const __half* __restrict__ FB,
                                   const float* __restrict__ EL,
                                   const float* __restrict__ ER,
                                   const int* __restrict__ rowptr,
                                   const int* __restrict__ srcs,
                                   const float* __restrict__ RESP,
                                   const float* __restrict__ B,
                                   float* __restrict__ OUT,
                                   int* __restrict__ CNT, int n) {
    constexpr int HD  = H * D;
    constexpr int VPL = HD / 32;     // 4 (HD=128) or 2 (HD=64)
    int gw = (blockIdx.x * blockDim.x + threadIdx.x) >> 5;
    if (gw >= n) return;
    int lane = threadIdx.x & 31;
    if (CNT && lane == 0) CNT[gw] = 0;

    constexpr int DSHIFT = (D == 16) ? 4 : 6;
    int col  = lane * VPL;
    int head = col >> DSHIFT;
    float erh = ER[gw * H + head];
    int beg = rowptr[gw], end = rowptr[gw + 1];

    float den = 0.f;
    float acc[VPL];
    #pragma unroll
    for (int j = 0; j < VPL; j++) acc[j] = 0.f;

    int i = beg;
    if (i + 8 <= end) {
        int s[8];
        #pragma unroll
        for (int u = 0; u < 8; u++) s[u] = srcs[i + u];
        while (true) {
            int ni = i + 8;
            bool haveN = (ni + 8 <= end);
            int sn[8];
            if (haveN) {
                #pragma unroll
                for (int u = 0; u < 8; u++) sn[u] = srcs[ni + u];
            }
            float elv[8];
            #pragma unroll
            for (int u = 0; u < 8; u++) elv[u] = EL[s[u] * H + head];
            if constexpr (VPL == 4) {
                uint2 v[8];
                #pragma unroll
                for (int u = 0; u < 8; u++)
                    v[u] = *reinterpret_cast<const uint2*>(FB + (size_t)s[u] * HD + col);
                #pragma unroll
                for (int u = 0; u < 8; u++) {
                    float x = elv[u] + erh;
                    x = x > 0.f ? x : 0.2f * x;
                    float a = __expf(x);
                    den += a;
                    float2 f01 = __half22float2(*reinterpret_cast<__half2*>(&v[u].x));
                    float2 f23 = __half22float2(*reinterpret_cast<__half2*>(&v[u].y));
                    acc[0] += f01.x * a; acc[1] += f01.y * a;
                    acc[2] += f23.x * a; acc[3] += f23.y * a;
                }
            } else {
                unsigned int v[8];
                #pragma unroll
                for (int u = 0; u < 8; u++)
                    v[u] = *reinterpret_cast<const unsigned int*>(FB + (size_t)s[u] * HD + col);
                #pragma unroll
                for (int u = 0; u < 8; u++) {
                    float x = elv[u] + erh;
                    x = x > 0.f ? x : 0.2f * x;
                    float a = __expf(x);
                    den += a;
                    float2 f01 = __half22float2(*reinterpret_cast<__half2*>(&v[u]));
                    acc[0] += f01.x * a; acc[1] += f01.y * a;
                }
            }
            i = ni;
            if (!haveN) break;
            #pragma unroll
            for (int u = 0; u < 8; u++) s[u] = sn[u];
        }
    }
    for (; i < end; i++) {
        int s0 = srcs[i];
        float x = EL[s0 * H + head] + erh;
        x = x > 0.f ? x : 0.2f * x;
        float a = __expf(x);
        den += a;
        if constexpr (VPL == 4) {
            uint2 v = *reinterpret_cast<const uint2*>(FB + (size_t)s0 * HD + col);
            float2 f01 = __half22float2(*reinterpret_cast<__half2*>(&v.x));
            float2 f23 = __half22float2(*reinterpret_cast<__half2*>(&v.y));
            acc[0] += f01.x * a; acc[1] += f01.y * a;
            acc[2] += f23.x * a; acc[3] += f23.y * a;
        } else {
            unsigned int v = *reinterpret_cast<const unsigned int*>(FB + (size_t)s0 * HD + col);
            float2 f01 = __half22float2(*reinterpret_cast<__half2*>(&v));
            acc[0] += f01.x * a; acc[1] += f01.y * a;
        }
    }

    float sinv = (end > beg) ? 1.0f / den : 0.0f;

    float o[VPL];
    #pragma unroll
    for (int j = 0; j < VPL; j++) {
        float v = acc[j] * sinv + B[col + j];
        if constexpr (HAS_RES) v += RESP[gw * HD + col + j];
        if constexpr (ELU_ACT) v = v > 0.f ? v : expm1f(v);
        o[j] = v;
    }
    if constexpr (VPL == 4)
        *reinterpret_cast<float4*>(OUT + gw * HD + col) = make_float4(o[0], o[1], o[2], o[3]);
    else
        *reinterpret_cast<float2*>(OUT + gw * HD + col) = make_float2(o[0], o[1]);
}

// ---------------- launch ----------------
extern "C" void kernel_launch(void* const* d_in, const int* in_sizes, int n_in,
                              void* d_out, int out_size) {
    const float* x     = (const float*)d_in[0];
    const int*   src   = (const int*)d_in[1];
    const int*   dst   = (const int*)d_in[2];
    const float* W0    = (const float*)d_in[3];
    const float* al0   = (const float*)d_in[4];
    const float* ar0   = (const float*)d_in[5];
    const float* b0    = (const float*)d_in[6];
    const float* W1    = (const float*)d_in[7];
    const float* al1   = (const float*)d_in[8];
    const float* ar1   = (const float*)d_in[9];
    const float* b1    = (const float*)d_in[10];
    const float* W2    = (const float*)d_in[11];
    const float* al2   = (const float*)d_in[12];
    const float* ar2   = (const float*)d_in[13];
    const float* b2    = (const float*)d_in[14];
    const float* resW2 = (const float*)d_in[15];
    float* out = (float*)d_out;

    const int n = NN;
    const int e = in_sizes[1];

    void* p;
    cudaGetSymbolAddress(&p, g_fb);     __half* fb_  = (__half*)p;
    cudaGetSymbolAddress(&p, g_h1);     float* h1_   = (float*)p;
    cudaGetSymbolAddress(&p, g_h2);     float* h2_   = (float*)p;
    cudaGetSymbolAddress(&p, g_res2);   float* res2_ = (float*)p;
    cudaGetSymbolAddress(&p, g_el);     float* el_   = (float*)p;
    cudaGetSymbolAddress(&p, g_er);     float* er_   = (float*)p;
    cudaGetSymbolAddress(&p, g_cnt);    int*   cnt_  = (int*)p;
    cudaGetSymbolAddress(&p, g_rowptr); int*   rp_   = (int*)p;
    cudaGetSymbolAddress(&p, g_cursor); int*   cur_  = (int*)p;
    cudaGetSymbolAddress(&p, g_bsum);   int*   bs_   = (int*)p;
    cudaGetSymbolAddress(&p, g_srcs);   int*   srcs_ = (int*)p;

    const int TB = 256;
    int nb_n   = (n + TB - 1) / TB;
    int nb_e   = (e + TB - 1) / TB;
    int nb_w   = (n + 7) / 8;
    int nb_sc  = (n + 1023) / 1024;
    int nb_g   = (n + 63) / 64;

    // ---- CSR build: hist(0), scan_local(1), scan_add2(2), scatter(3) ----
    // cnt is zero at entry (static init on first call; restored by the final
    // fused kernel on every call).
    hist_kernel<<<nb_e, TB>>>(dst, cnt_, e);
    scan_local_kernel<<<nb_sc, 256>>>(cnt_, rp_, bs_, n);
    scan_add2_kernel<<<nb_n, TB>>>(bs_, nb_sc, rp_, cur_, n);
    scatter_kernel<<<nb_e, TB>>>(src, dst, cur_, srcs_, e);

    // ---- layer 0: gemm(4), fused(5) ----
    gemm2_kernel<false><<<nb_g, 256>>>(x, W0, nullptr, al0, ar0,
                                       nullptr, el_, er_, fb_, n);
    fused_layer_kernel<8, 16, true, false><<<nb_w, TB>>>(fb_, el_, er_, rp_, srcs_,
                                                         nullptr, b0, h1_, nullptr, n);

    // ---- layer 1: identity residual, ELU ----
    gemm2_kernel<false><<<nb_g, 256>>>(h1_, W1, nullptr, al1, ar1,
                                       nullptr, el_, er_, fb_, n);
    fused_layer_kernel<8, 16, true, true><<<nb_w, TB>>>(fb_, el_, er_, rp_, srcs_,
                                                        h1_, b1, h2_, nullptr, n);

    // ---- layer 2: dual GEMM (W2 + resW2), no act; fused zeroes cnt ----
    gemm2_kernel<true><<<nb_g, 256>>>(h2_, W2, resW2, al2, ar2,
                                      res2_, el_, er_, fb_, n);
    fused_layer_kernel<1, 64, false, true><<<nb_w, TB>>>(fb_, el_, er_, rp_, srcs_,
                                                         res2_, b2, out, cnt_, n);
}